// round 3
// baseline (speedup 1.0000x reference)
#include <cuda_runtime.h>
#include <math.h>

#define K_SIZE 41
#define WBLK   256
// blocks = 41 * GRID_MULT; 41*28 = 1148 <= 1184 (148 SMs * 8 blocks of 256 thr)
// => exactly one wave, and stride = 1148*256 = 293888 = 41 * 7168  (== 0 mod 41)
#define GRID_MULT 28
#define NBLOCKS   (K_SIZE * GRID_MULT)

// ---------------------------------------------------------------------------
// Single fused kernel. Every block:
//   1. loads the 41-float window + scale (L2-broadcast after first wave),
//      computes base[41] = masked circular max, expands to float4 pattern
//   2. grid-strides over the output in float4 units with a stride that is
//      a multiple of 41, so each thread's pattern value is loop-invariant
//      and lives in registers: hot loop = STG.128 + IADD + branch only.
// Block 0 thread 0 additionally writes the <=3 scalar tail elements.
// ---------------------------------------------------------------------------
__global__ void __launch_bounds__(WBLK)
flatdil_fused_kernel(const float* __restrict__ in,
                     const float* __restrict__ scale_p,
                     float* __restrict__ out,
                     long long n)
{
    __shared__ float  s_pad[K_SIZE];
    __shared__ float  s_base[K_SIZE];
    __shared__ float4 s_pat[K_SIZE];

    const int t = threadIdx.x;

    // ---- compute base[41] (redundantly per block; input is tiny) ----
    // Python: missing = K_SIZE - n; a = -(missing // 2 + 2)  (floor division)
    const long long missing = (long long)K_SIZE - n;
    const long long a = -((missing >> 1) + 2);   // arithmetic shift == floor div

    if (t < K_SIZE) {
        s_pad[t] = in[a + (long long)t];
    }
    __syncthreads();

    if (t < K_SIZE) {
        const float scale = *scale_p;
        float acc = -INFINITY;
        #pragma unroll
        for (int j = 0; j < K_SIZE; ++j) {
            // z[j] = -20 + j  (linspace(-20,20,41) has exact unit step)
            const float zj = (float)(j - 20);
            if (fabsf(zj) <= scale) {
                int idx = t + j;
                if (idx >= K_SIZE) idx -= K_SIZE;
                acc = fmaxf(acc, s_pad[idx]);
            }
        }
        s_base[t] = acc;
    }
    __syncthreads();

    if (t < K_SIZE) {
        // s_pat[p] covers output floats 4p..4p+3 (pattern period in float4s = 41)
        int i0 = (4 * t) % K_SIZE;
        int i1 = i0 + 1; if (i1 >= K_SIZE) i1 -= K_SIZE;
        int i2 = i1 + 1; if (i2 >= K_SIZE) i2 -= K_SIZE;
        int i3 = i2 + 1; if (i3 >= K_SIZE) i3 -= K_SIZE;
        float4 v;
        v.x = s_base[i0];
        v.y = s_base[i1];
        v.z = s_base[i2];
        v.w = s_base[i3];
        s_pat[t] = v;
    }
    __syncthreads();

    const unsigned int n4 = (unsigned int)(n >> 2);   // full float4 count

    // ---- scalar tail (<= 3 elements) ----
    if (blockIdx.x == 0 && t == 0) {
        for (long long k = (long long)n4 * 4; k < n; ++k) {
            out[k] = s_base[(int)(k % K_SIZE)];
        }
    }

    // ---- streaming store loop: stride == 0 (mod 41), value loop-invariant ----
    float4* __restrict__ out4 = (float4*)out;
    const unsigned int stride = gridDim.x * WBLK;      // 293888 = 41*7168
    unsigned int i = blockIdx.x * WBLK + (unsigned int)t;

    if (i < n4) {
        const float4 v = s_pat[i % K_SIZE];            // computed ONCE per thread
        #pragma unroll 4
        for (; i < n4; i += stride) {
            out4[i] = v;                               // pure STG.128
        }
    }
}

// ---------------------------------------------------------------------------
extern "C" void kernel_launch(void* const* d_in, const int* in_sizes, int n_in,
                              void* d_out, int out_size)
{
    const float* in      = (const float*)d_in[0];
    const float* scale_p = (const float*)d_in[1];
    float* out           = (float*)d_out;

    const long long n = (long long)in_sizes[0];

    flatdil_fused_kernel<<<NBLOCKS, WBLK>>>(in, scale_p, out, n);
}